// round 3
// baseline (speedup 1.0000x reference)
#include <cuda_runtime.h>

// Analytic collapse of the 16-qubit circuit (rounds 1-2):
//   theta = x @ W_in^T + b_in
//   e[b,k] = prod_{j<=k, (k-j)%4 in {0,1}} cos(theta[b,j])
//   out    = e @ W_out^T + b_out
// q_weights provably cannot affect the output (diagonal phases + permutations).
//
// R3: one warp per batch row, no smem, no __syncthreads. The mask set for
// e[k] is {j<=k : j = k or k-1 (mod 4)}, so with residue-class prefix
// products A_r: e[k] = A_{k%4}(k) * A_{(k-1)%4}(k-1) -> 16 serial FMULs.

__global__ void __launch_bounds__(128) quantum_layer_kernel(
    const float4* __restrict__ x4,    // (256, 32) float4
    const float4* __restrict__ Wi4,   // (16, 32)  float4
    const float*  __restrict__ b_in,  // (16)
    const float4* __restrict__ Wo4,   // (128, 4)  float4
    const float4* __restrict__ bo4,   // (32)      float4
    float4* __restrict__ out4)        // (256, 32) float4
{
    const int warp = threadIdx.x >> 5;
    const int lane = threadIdx.x & 31;
    const int b    = (blockIdx.x << 2) + warp;   // one warp per batch row
    const int q    = lane >> 1;                  // 2 lanes per qubit
    const int h    = lane & 1;                   // which 64-element half

    // ---- Preload epilogue operands: W_out rows 4*lane..4*lane+3 (16xLDG.128)
    // and bias. Independent of everything -> latency hides under the dot. ----
    float4 wreg[4][4];
    #pragma unroll
    for (int s = 0; s < 4; ++s)
        #pragma unroll
        for (int i = 0; i < 4; ++i)
            wreg[s][i] = Wo4[(lane * 4 + s) * 4 + i];
    float4 o = bo4[lane];
    const float bq = b_in[q];

    // ---- theta[b,q]: each lane does a 64-element dot (16 x-float4, 16 w-float4). ----
    const float4* xp = x4  + b * 32 + h * 16;
    const float4* wp = Wi4 + q * 32 + h * 16;
    float a0 = 0.f, a1 = 0.f, a2 = 0.f, a3 = 0.f;
    #pragma unroll
    for (int i = 0; i < 16; i += 4) {
        float4 xa = xp[i+0], wa = wp[i+0];
        float4 xb = xp[i+1], wb = wp[i+1];
        float4 xc = xp[i+2], wc = wp[i+2];
        float4 xd = xp[i+3], wd = wp[i+3];
        a0 += xa.x*wa.x + xa.y*wa.y + xa.z*wa.z + xa.w*wa.w;
        a1 += xb.x*wb.x + xb.y*wb.y + xb.z*wb.z + xb.w*wb.w;
        a2 += xc.x*wc.x + xc.y*wc.y + xc.z*wc.z + xc.w*wc.w;
        a3 += xd.x*wd.x + xd.y*wd.y + xd.z*wd.z + xd.w*wd.w;
    }
    float p = (a0 + a1) + (a2 + a3);
    p += __shfl_xor_sync(0xffffffffu, p, 1);
    const float cq = __cosf(p + bq);             // both lanes of the pair hold cs[q]

    // ---- All-gather the 16 cosines (independent shfls, pipelined). ----
    float cs[16];
    #pragma unroll
    for (int j = 0; j < 16; ++j)
        cs[j] = __shfl_sync(0xffffffffu, cq, j << 1);

    // ---- Expvals via residue-class prefix products (per-lane, registers). ----
    float A[4] = {1.f, 1.f, 1.f, 1.f};
    float e[16];
    float prev = 1.f;                            // A_{(k-1)%4}(k-1)
    #pragma unroll
    for (int k = 0; k < 16; ++k) {
        A[k & 3] *= cs[k];
        e[k] = A[k & 3] * prev;
        prev = A[k & 3];
    }

    // ---- out[b, 4*lane+s] = b_out + sum_k e[k] * W_out[4*lane+s, k]. ----
    float* oc = &o.x;
    #pragma unroll
    for (int s = 0; s < 4; ++s) {
        float acc = oc[s];
        #pragma unroll
        for (int i = 0; i < 4; ++i) {
            acc = fmaf(e[4*i+0], wreg[s][i].x, acc);
            acc = fmaf(e[4*i+1], wreg[s][i].y, acc);
            acc = fmaf(e[4*i+2], wreg[s][i].z, acc);
            acc = fmaf(e[4*i+3], wreg[s][i].w, acc);
        }
        oc[s] = acc;
    }
    out4[b * 32 + lane] = o;                      // STG.128
}

extern "C" void kernel_launch(void* const* d_in, const int* in_sizes, int n_in,
                              void* d_out, int out_size) {
    const float4* x4    = (const float4*)d_in[0];  // (256,128)
    const float4* Wi4   = (const float4*)d_in[1];  // (16,128)
    const float*  b_in  = (const float*)d_in[2];   // (16)
    // d_in[3] = q_weights — provably no effect on output.
    const float4* Wo4   = (const float4*)d_in[4];  // (128,16)
    const float4* bo4   = (const float4*)d_in[5];  // (128)
    float4* out4 = (float4*)d_out;

    quantum_layer_kernel<<<64, 128>>>(x4, Wi4, b_in, Wo4, bo4, out4);
}

// round 4
// speedup vs baseline: 1.3413x; 1.3413x over previous
#include <cuda_runtime.h>

// Analytic collapse of the 16-qubit circuit (rounds 1-3):
//   theta = x @ W_in^T + b_in
//   e[b,k] = prod_{j<=k, (k-j)%4 in {0,1}} cos(theta[b,j])
//        = A_{k%4}(k) * A_{(k-1)%4}(k-1)   (residue-class prefix products)
//   out    = e @ W_out^T + b_out
// q_weights provably cannot affect the output (diagonal phases + permutations).
//
// R4: single wave (128 CTAs x 256 thr), two independent 128-thread row-groups
// per CTA synced by named barriers; one barrier per row; per-thread prefix
// chains replace the smem expval exchange.

__global__ void __launch_bounds__(256) quantum_layer_kernel(
    const float4* __restrict__ x4,    // (256, 32) float4
    const float4* __restrict__ Wi4,   // (16, 32)  float4
    const float*  __restrict__ b_in,  // (16)
    const float4* __restrict__ Wo4,   // (128, 4)  float4
    const float*  __restrict__ b_out, // (128)
    float* __restrict__ out)          // (256, 128)
{
    __shared__ float cs[2][16];

    const int t  = threadIdx.x;
    const int g  = t >> 7;            // row-group within CTA (0/1)
    const int tt = t & 127;           // thread within group
    const int b  = (blockIdx.x << 1) + g;
    const int q  = tt >> 3;           // 16 qubits, 8 lanes each
    const int e8 = tt & 7;

    // ---- Preload epilogue operands (independent -> hides under the dot). ----
    const float4* wo = Wo4 + tt * 4;
    const float4 w0 = wo[0], w1 = wo[1], w2 = wo[2], w3 = wo[3];
    const float  bo = b_out[tt];
    const float  bq = b_in[q];

    // ---- theta[b,q]: 8 lanes x 16 elements (4x LDG.128 each). ----
    const float4* xp = x4  + b * 32 + e8 * 4;
    const float4* wp = Wi4 + q * 32 + e8 * 4;
    float4 xa = xp[0], wa = wp[0];
    float4 xb = xp[1], wb = wp[1];
    float4 xc = xp[2], wc = wp[2];
    float4 xd = xp[3], wd = wp[3];
    float p0 = xa.x*wa.x + xa.y*wa.y + xa.z*wa.z + xa.w*wa.w;
    float p1 = xb.x*wb.x + xb.y*wb.y + xb.z*wb.z + xb.w*wb.w;
    float p2 = xc.x*wc.x + xc.y*wc.y + xc.z*wc.z + xc.w*wc.w;
    float p3 = xd.x*wd.x + xd.y*wd.y + xd.z*wd.z + xd.w*wd.w;
    float p = (p0 + p1) + (p2 + p3);
    p += __shfl_down_sync(0xffffffffu, p, 4, 8);
    p += __shfl_down_sync(0xffffffffu, p, 2, 8);
    p += __shfl_down_sync(0xffffffffu, p, 1, 8);
    if (e8 == 0) cs[g][q] = __cosf(p + bq);      // MUFU; |theta| small, tol 1e-3

    // Named barrier per 128-thread group: groups don't couple.
    asm volatile("bar.sync %0, 128;" :: "r"(1 + g) : "memory");

    // ---- Every thread: prefix chains -> expvals in registers (no 2nd bar). ----
    float c[16];
    #pragma unroll
    for (int j = 0; j < 16; j += 4) {
        float4 v = *reinterpret_cast<const float4*>(&cs[g][j]);  // LDS.128 broadcast
        c[j] = v.x; c[j+1] = v.y; c[j+2] = v.z; c[j+3] = v.w;
    }
    float A0 = 1.f, A1 = 1.f, A2 = 1.f, A3 = 1.f;
    float e[16];
    float prev = 1.f;
    #pragma unroll
    for (int k = 0; k < 16; ++k) {
        float* Ar = (k & 3) == 0 ? &A0 : (k & 3) == 1 ? &A1 : (k & 3) == 2 ? &A2 : &A3;
        *Ar *= c[k];
        e[k] = *Ar * prev;
        prev = *Ar;
    }

    // ---- out[b,tt] = b_out[tt] + sum_k e[k] * W_out[tt,k]. ----
    float acc = bo;
    acc = fmaf(e[0],  w0.x, acc); acc = fmaf(e[1],  w0.y, acc);
    acc = fmaf(e[2],  w0.z, acc); acc = fmaf(e[3],  w0.w, acc);
    acc = fmaf(e[4],  w1.x, acc); acc = fmaf(e[5],  w1.y, acc);
    acc = fmaf(e[6],  w1.z, acc); acc = fmaf(e[7],  w1.w, acc);
    acc = fmaf(e[8],  w2.x, acc); acc = fmaf(e[9],  w2.y, acc);
    acc = fmaf(e[10], w2.z, acc); acc = fmaf(e[11], w2.w, acc);
    acc = fmaf(e[12], w3.x, acc); acc = fmaf(e[13], w3.y, acc);
    acc = fmaf(e[14], w3.z, acc); acc = fmaf(e[15], w3.w, acc);
    out[b * 128 + tt] = acc;
}

extern "C" void kernel_launch(void* const* d_in, const int* in_sizes, int n_in,
                              void* d_out, int out_size) {
    const float4* x4    = (const float4*)d_in[0];  // (256,128)
    const float4* Wi4   = (const float4*)d_in[1];  // (16,128)
    const float*  b_in  = (const float*)d_in[2];   // (16)
    // d_in[3] = q_weights — provably no effect on output.
    const float4* Wo4   = (const float4*)d_in[4];  // (128,16)
    const float*  b_out = (const float*)d_in[5];   // (128)
    float* out = (float*)d_out;

    quantum_layer_kernel<<<128, 256>>>(x4, Wi4, b_in, Wo4, b_out, out);
}